// round 6
// baseline (speedup 1.0000x reference)
#include <cuda_runtime.h>
#include <cuda_bf16.h>
#include <cstdint>

#define Nn 2048
#define Mm 10
#define Dd 256
#define ROWS (Nn * Mm)      // 20480

#define QS 320.0f           // int8 quantization scale
#define QS2INV (1.0f / (QS * QS))

// ---------------------------------------------------------------------------
// Scratch (device globals; no allocation allowed)
// ---------------------------------------------------------------------------
__device__ __align__(16) int8_t g_A[(size_t)ROWS * Dd];  // quantized normalized emb
__device__ __align__(16) int8_t g_B[(size_t)Nn * Dd];    // quantized centroids
__device__ float g_rowsum[ROWS];
__device__ float g_pos[ROWS];   // stores t = |w|*(cos-1); shift cancels in lse-pos

__device__ __forceinline__ uint32_t smem_u32(const void* p) {
    uint32_t a;
    asm("{ .reg .u64 t; cvta.to.shared.u64 t, %1; cvt.u32.u64 %0, t; }" : "=r"(a) : "l"(p));
    return a;
}
__device__ __forceinline__ void cpa16(uint32_t dst, const void* src) {
    asm volatile("cp.async.cg.shared.global [%0], [%1], 16;" :: "r"(dst), "l"(src));
}
__device__ __forceinline__ void ldm_x4(uint32_t* r, uint32_t addr) {
    asm volatile("ldmatrix.sync.aligned.m8n8.x4.shared.b16 {%0,%1,%2,%3}, [%4];"
                 : "=r"(r[0]), "=r"(r[1]), "=r"(r[2]), "=r"(r[3]) : "r"(addr));
}
__device__ __forceinline__ void mma_s8(int* c, const uint32_t* a,
                                       uint32_t b0, uint32_t b1) {
    asm volatile(
        "mma.sync.aligned.m16n8k32.row.col.s32.s8.s8.s32 "
        "{%0,%1,%2,%3}, {%4,%5,%6,%7}, {%8,%9}, {%0,%1,%2,%3};"
        : "+r"(c[0]), "+r"(c[1]), "+r"(c[2]), "+r"(c[3])
        : "r"(a[0]), "r"(a[1]), "r"(a[2]), "r"(a[3]), "r"(b0), "r"(b1));
}
__device__ __forceinline__ int q8(float v) {
    int i = __float2int_rn(v * QS);
    return max(-127, min(127, i));
}
__device__ __forceinline__ uint32_t pack4(float a, float b, float c, float d) {
    return (uint32_t)(q8(a) & 0xFF) | ((uint32_t)(q8(b) & 0xFF) << 8) |
           ((uint32_t)(q8(c) & 0xFF) << 16) | ((uint32_t)(q8(d) & 0xFF) << 24);
}

// ---------------------------------------------------------------------------
// Kernel 1: prep. One block per speaker n, 320 threads (warp m = utterance m).
// Quantizes normalized rows / centroids to int8 with scale QS.
// ---------------------------------------------------------------------------
__global__ void __launch_bounds__(320) prep_kernel(const float* __restrict__ emb) {
    const int n = blockIdx.x;
    const int tid = threadIdx.x;
    const int w = tid >> 5, lane = tid & 31;
    __shared__ float sv[Mm][Dd];
    __shared__ float warp_red[8];
    __shared__ float cnorm;

    {   // per-utterance L2 normalize -> int8 (lane handles cols lane*8..+7)
        const float* src = emb + ((size_t)n * Mm + w) * Dd;
        float4 x0 = *(const float4*)(src + lane * 8);
        float4 x1 = *(const float4*)(src + lane * 8 + 4);
        float ss = x0.x * x0.x + x0.y * x0.y + x0.z * x0.z + x0.w * x0.w
                 + x1.x * x1.x + x1.y * x1.y + x1.z * x1.z + x1.w * x1.w;
#pragma unroll
        for (int off = 16; off > 0; off >>= 1) ss += __shfl_xor_sync(0xffffffffu, ss, off);
        float sc = 1.f / fmaxf(sqrtf(ss), 1e-12f);
        uint2 pk;
        pk.x = pack4(x0.x * sc, x0.y * sc, x0.z * sc, x0.w * sc);
        pk.y = pack4(x1.x * sc, x1.y * sc, x1.z * sc, x1.w * sc);
        *(uint2*)(g_A + (size_t)(n * Mm + w) * Dd + lane * 8) = pk;
        *(float4*)&sv[w][lane * 8] = x0;
        *(float4*)&sv[w][lane * 8 + 4] = x1;
    }
    __syncthreads();

    // centroid = l2norm(sum_m emb) (scale-invariant; skip /M)
    float s = 0.f;
    if (tid < Dd) {
#pragma unroll
        for (int m = 0; m < Mm; m++) s += sv[m][tid];
        float ss = s * s;
#pragma unroll
        for (int off = 16; off > 0; off >>= 1) ss += __shfl_xor_sync(0xffffffffu, ss, off);
        if (lane == 0) warp_red[tid >> 5] = ss;
    }
    __syncthreads();
    if (tid == 0) {
        float t = 0.f;
#pragma unroll
        for (int i = 0; i < 8; i++) t += warp_red[i];
        cnorm = fmaxf(sqrtf(t), 1e-12f);
    }
    __syncthreads();
    if (tid < Dd) g_B[(size_t)n * Dd + tid] = (int8_t)q8(s / cnorm);
    if (tid < Mm) g_rowsum[n * Mm + tid] = 0.f;   // graph-replay-safe zeroing
}

// ---------------------------------------------------------------------------
// Kernel 2: int8 IMMA GEMM, CTA tile 128x128, 16 warps (4x4), warp tile 32x32.
// BK=32 (one m16n8k32 K-step per chunk), 3-stage cp.async pipeline.
// Static smem 36,864B -> 2 CTAs/SM = 32 warps/SM.
// Fused epilogue: t = |w|*(acc/QS^2 - 1); rowsum += exp(t); pos = t.
// ---------------------------------------------------------------------------
#define BK 32
#define SROW 48                       // padded row stride, bytes (32 + 16 pad)
#define NCHUNK (Dd / BK)              // 8
#define STG (128 * SROW)              // 6144 B per tile stage

__global__ void __launch_bounds__(512, 2)
gemm_lse_kernel(const float* __restrict__ wp, const float* __restrict__ bp) {
    __shared__ int8_t smem[6 * STG];  // [A0 A1 A2 | B0 B1 B2]
    const uint32_t as0 = smem_u32(smem);
    const uint32_t bs0 = as0 + 3 * STG;

    const int tid = threadIdx.x;
    const int wid = tid >> 5, lane = tid & 31;
    const int wm = wid >> 2;          // 0..3  (32-row slice)
    const int wn = wid & 3;           // 0..3  (32-col slice)
    const int r0 = blockIdx.y * 128;
    const int c0 = blockIdx.x * 128;

    // loader: 512 threads, 1 cp.async each per chunk (A:256, B:256)
    const int ltile = tid >> 8;       // 0 = A, 1 = B
    const int lrow = (tid >> 1) & 127;
    const int lhalf = tid & 1;        // 16B half of the 32B row-chunk

    auto load_chunk = [&](int c, int stg) {
        const int8_t* src = ltile
            ? g_B + (size_t)(c0 + lrow) * Dd + c * BK + lhalf * 16
            : g_A + (size_t)(r0 + lrow) * Dd + c * BK + lhalf * 16;
        uint32_t dst = (ltile ? bs0 : as0) + stg * STG + lrow * SROW + lhalf * 16;
        cpa16(dst, src);
        asm volatile("cp.async.commit_group;" ::: "memory");
    };

    int acc[2][4][4] = {};

    load_chunk(0, 0);
    load_chunk(1, 1);

#pragma unroll
    for (int c = 0; c < NCHUNK; c++) {
        if (c <= 6) asm volatile("cp.async.wait_group 1;" ::: "memory");
        else        asm volatile("cp.async.wait_group 0;" ::: "memory");
        __syncthreads();
        if (c + 2 < NCHUNK) load_chunk(c + 2, (c + 2) % 3);

        const uint32_t ab = as0 + (c % 3) * STG;
        const uint32_t bb = bs0 + (c % 3) * STG;

        uint32_t a[2][4];
#pragma unroll
        for (int mt = 0; mt < 2; mt++) {
            int row = wm * 32 + mt * 16 + (lane & 15);
            ldm_x4(a[mt], ab + row * SROW + (lane >> 4) * 16);
        }
        uint32_t b[2][4];
#pragma unroll
        for (int ng = 0; ng < 2; ng++) {
            int row = wn * 32 + ng * 16 + (lane & 7) + ((lane >> 4) & 1) * 8;
            ldm_x4(b[ng], bb + row * SROW + ((lane >> 3) & 1) * 16);
        }
#pragma unroll
        for (int mt = 0; mt < 2; mt++)
#pragma unroll
            for (int nt = 0; nt < 4; nt++)
                mma_s8(acc[mt][nt], a[mt],
                       b[nt >> 1][(nt & 1) * 2], b[nt >> 1][(nt & 1) * 2 + 1]);
    }

    // ---- fused epilogue: t = (|w|/QS^2)*acc - |w|; rowsum += exp(t) ----
    const float wabs = fabsf(*wp);
    const float scale = wabs * QS2INV;
    const float nw = -wabs;
    const int q = lane >> 2, qi = lane & 3;
    const int cbase = c0 + wn * 32;

#pragma unroll
    for (int mt = 0; mt < 2; mt++) {
        const int rowA = r0 + wm * 32 + mt * 16 + q;
        const int rowB = rowA + 8;
        const int posA = rowA / Mm, posB = rowB / Mm;
        float sA = 0.f, sB = 0.f;
#pragma unroll
        for (int nt = 0; nt < 4; nt++) {
            const int col = cbase + nt * 8 + qi * 2;
            float t0 = fmaf(scale, (float)acc[mt][nt][0], nw);
            float t1 = fmaf(scale, (float)acc[mt][nt][1], nw);
            float t2 = fmaf(scale, (float)acc[mt][nt][2], nw);
            float t3 = fmaf(scale, (float)acc[mt][nt][3], nw);
            sA += __expf(t0) + __expf(t1);
            sB += __expf(t2) + __expf(t3);
            if (col == posA) g_pos[rowA] = t0;
            if (col + 1 == posA) g_pos[rowA] = t1;
            if (col == posB) g_pos[rowB] = t2;
            if (col + 1 == posB) g_pos[rowB] = t3;
        }
#pragma unroll
        for (int off = 2; off > 0; off >>= 1) {
            sA += __shfl_xor_sync(0xffffffffu, sA, off);
            sB += __shfl_xor_sync(0xffffffffu, sB, off);
        }
        if (qi == 0) {
            atomicAdd(&g_rowsum[rowA], sA);
            atomicAdd(&g_rowsum[rowB], sB);
        }
    }
}

// ---------------------------------------------------------------------------
// Kernel 3: loss = mean_r( log(rowsum[r]) - pos_t[r] )   (shift cancels)
// ---------------------------------------------------------------------------
__global__ void loss_kernel(float* __restrict__ out) {
    __shared__ float red[256];
    float s = 0.f;
    for (int r = threadIdx.x; r < ROWS; r += 256)
        s += __logf(g_rowsum[r]) - g_pos[r];
    red[threadIdx.x] = s;
    __syncthreads();
    for (int off = 128; off > 0; off >>= 1) {
        if (threadIdx.x < off) red[threadIdx.x] += red[threadIdx.x + off];
        __syncthreads();
    }
    if (threadIdx.x == 0) out[0] = red[0] / (float)ROWS;
}

// ---------------------------------------------------------------------------
extern "C" void kernel_launch(void* const* d_in, const int* in_sizes, int n_in,
                              void* d_out, int out_size) {
    const float* emb = (const float*)d_in[0];
    const float* w   = (const float*)d_in[1];
    const float* b   = (const float*)d_in[2];
    (void)b;
    float* out = (float*)d_out;

    prep_kernel<<<Nn, 320>>>(emb);
    gemm_lse_kernel<<<dim3(Nn / 128, ROWS / 128), 512>>>(w, b);
    loss_kernel<<<1, 256>>>(out);
}

// round 7
// speedup vs baseline: 1.9973x; 1.9973x over previous
#include <cuda_runtime.h>
#include <cuda_fp16.h>
#include <cstdint>

#define Nn 2048
#define Mm 10
#define Dd 256
#define ROWS (Nn * Mm)      // 20480

// ---------------------------------------------------------------------------
// Scratch (device globals; no allocation allowed)
// ---------------------------------------------------------------------------
__device__ __align__(16) __half g_A[(size_t)ROWS * Dd];  // normalized emb, fp16
__device__ __align__(16) __half g_B[(size_t)Nn * Dd];    // normalized centroids, fp16
__device__ float g_rowsum[ROWS];
__device__ float g_pos[ROWS];   // stores t = |w|*(cos-1); shift cancels in lse-pos

__device__ __forceinline__ uint32_t smem_u32(const void* p) {
    uint32_t a;
    asm("{ .reg .u64 t; cvta.to.shared.u64 t, %1; cvt.u32.u64 %0, t; }" : "=r"(a) : "l"(p));
    return a;
}
__device__ __forceinline__ void cpa16(uint32_t dst, const void* src) {
    asm volatile("cp.async.cg.shared.global [%0], [%1], 16;" :: "r"(dst), "l"(src));
}
__device__ __forceinline__ void ldm_x4(uint32_t* r, uint32_t addr) {
    asm volatile("ldmatrix.sync.aligned.m8n8.x4.shared.b16 {%0,%1,%2,%3}, [%4];"
                 : "=r"(r[0]), "=r"(r[1]), "=r"(r[2]), "=r"(r[3]) : "r"(addr));
}
// fp16 inputs, fp16 accumulator (2 packed .f16x2 regs)
__device__ __forceinline__ void mma_f16acc(uint32_t* c, const uint32_t* a,
                                           uint32_t b0, uint32_t b1) {
    asm volatile(
        "mma.sync.aligned.m16n8k16.row.col.f16.f16.f16.f16 "
        "{%0,%1}, {%2,%3,%4,%5}, {%6,%7}, {%0,%1};"
        : "+r"(c[0]), "+r"(c[1])
        : "r"(a[0]), "r"(a[1]), "r"(a[2]), "r"(a[3]), "r"(b0), "r"(b1));
}

// ---------------------------------------------------------------------------
// Kernel 1: prep. One block per speaker n, 320 threads (warp m = utterance m).
// ---------------------------------------------------------------------------
__global__ void __launch_bounds__(320) prep_kernel(const float* __restrict__ emb) {
    const int n = blockIdx.x;
    const int tid = threadIdx.x;
    const int w = tid >> 5, lane = tid & 31;
    __shared__ float sv[Mm][Dd];
    __shared__ float warp_red[8];
    __shared__ float cnorm;

    {   // per-utterance L2 normalize -> fp16
        const float* src = emb + ((size_t)n * Mm + w) * Dd;
        float4 x0 = *(const float4*)(src + lane * 8);
        float4 x1 = *(const float4*)(src + lane * 8 + 4);
        float ss = x0.x * x0.x + x0.y * x0.y + x0.z * x0.z + x0.w * x0.w
                 + x1.x * x1.x + x1.y * x1.y + x1.z * x1.z + x1.w * x1.w;
#pragma unroll
        for (int off = 16; off > 0; off >>= 1) ss += __shfl_xor_sync(0xffffffffu, ss, off);
        float sc = 1.f / fmaxf(sqrtf(ss), 1e-12f);
        __half2 p0 = __floats2half2_rn(x0.x * sc, x0.y * sc);
        __half2 p1 = __floats2half2_rn(x0.z * sc, x0.w * sc);
        __half2 p2 = __floats2half2_rn(x1.x * sc, x1.y * sc);
        __half2 p3 = __floats2half2_rn(x1.z * sc, x1.w * sc);
        uint4 v{*(uint32_t*)&p0, *(uint32_t*)&p1, *(uint32_t*)&p2, *(uint32_t*)&p3};
        *(uint4*)(g_A + (size_t)(n * Mm + w) * Dd + lane * 8) = v;
        *(float4*)&sv[w][lane * 8] = x0;
        *(float4*)&sv[w][lane * 8 + 4] = x1;
    }
    __syncthreads();

    // centroid = l2norm(sum_m emb) (scale-invariant; skip /M)
    float s = 0.f;
    if (tid < Dd) {
#pragma unroll
        for (int m = 0; m < Mm; m++) s += sv[m][tid];
        float ss = s * s;
#pragma unroll
        for (int off = 16; off > 0; off >>= 1) ss += __shfl_xor_sync(0xffffffffu, ss, off);
        if (lane == 0) warp_red[tid >> 5] = ss;
    }
    __syncthreads();
    if (tid == 0) {
        float t = 0.f;
#pragma unroll
        for (int i = 0; i < 8; i++) t += warp_red[i];
        cnorm = fmaxf(sqrtf(t), 1e-12f);
    }
    __syncthreads();
    if (tid < Dd) g_B[(size_t)n * Dd + tid] = __float2half(s / cnorm);
    if (tid < Mm) g_rowsum[n * Mm + tid] = 0.f;   // graph-replay-safe zeroing
}

// ---------------------------------------------------------------------------
// Kernel 2: fp16 HMMA (fp16 accumulator), CTA tile 128x128, warp tile 64x32
// (2x4 warps), BK=32, 3-stage cp.async pipeline, one __syncthreads per chunk.
// Smem = 61,440 B dynamic -> 2 CTAs/SM (16 warps/SM).
// Fused epilogue: t = |w|*(cos-1); rowsum += exp(t); pos = t.
// ---------------------------------------------------------------------------
#define BK 32
#define SSTR 40                       // padded row stride (elems); 80B
#define NCHUNK (Dd / BK)              // 8
#define STG (128 * SSTR * 2)          // 10240 B per tile stage
#define SMEM_BYTES (3 * 2 * STG)      // 61440

__global__ void __launch_bounds__(256, 2)
gemm_lse_kernel(const float* __restrict__ wp, const float* __restrict__ bp) {
    extern __shared__ char smem[];
    const uint32_t as0 = smem_u32(smem);
    const uint32_t bs0 = as0 + 3 * STG;

    const int tid = threadIdx.x;
    const int wid = tid >> 5, lane = tid & 31;
    const int wm = wid & 1;           // 0..1  (64-row slice)
    const int wn = wid >> 1;          // 0..3  (32-col slice)
    const int r0 = blockIdx.y * 128;
    const int c0 = blockIdx.x * 128;

    const int lrow = tid >> 2;        // 0..63
    const int lquad = tid & 3;        // 16B quad within 64B of row-chunk

    auto load_chunk = [&](int c, int stg) {
#pragma unroll
        for (int i = 0; i < 2; i++) {
            int row = lrow + i * 64;
            cpa16(as0 + stg * STG + row * (SSTR * 2) + lquad * 16,
                  g_A + (size_t)(r0 + row) * Dd + c * BK + lquad * 8);
            cpa16(bs0 + stg * STG + row * (SSTR * 2) + lquad * 16,
                  g_B + (size_t)(c0 + row) * Dd + c * BK + lquad * 8);
        }
        asm volatile("cp.async.commit_group;" ::: "memory");
    };

    uint32_t acc[4][4][2] = {};   // fp16x2 accumulators (rows q / q+8)

    load_chunk(0, 0);
    load_chunk(1, 1);

#pragma unroll
    for (int c = 0; c < NCHUNK; c++) {
        if (c <= 6) asm volatile("cp.async.wait_group 1;" ::: "memory");
        else        asm volatile("cp.async.wait_group 0;" ::: "memory");
        __syncthreads();
        if (c + 2 < NCHUNK) load_chunk(c + 2, (c + 2) % 3);

        const uint32_t ab = as0 + (c % 3) * STG;
        const uint32_t bb = bs0 + (c % 3) * STG;
#pragma unroll
        for (int ks = 0; ks < 2; ks++) {
            const int k0 = ks * 16;
            uint32_t a[4][4];
#pragma unroll
            for (int mt = 0; mt < 4; mt++) {
                int row = wm * 64 + mt * 16 + (lane & 15);
                int col = k0 + (lane >> 4) * 8;
                ldm_x4(a[mt], ab + row * (SSTR * 2) + col * 2);
            }
            uint32_t b[2][4];
#pragma unroll
            for (int ng = 0; ng < 2; ng++) {
                int row = wn * 32 + ng * 16 + (lane & 7) + (lane >> 4) * 8;
                int col = k0 + ((lane >> 3) & 1) * 8;
                ldm_x4(b[ng], bb + row * (SSTR * 2) + col * 2);
            }
#pragma unroll
            for (int mt = 0; mt < 4; mt++)
#pragma unroll
                for (int nt = 0; nt < 4; nt++)
                    mma_f16acc(acc[mt][nt], a[mt],
                               b[nt >> 1][(nt & 1) * 2], b[nt >> 1][(nt & 1) * 2 + 1]);
        }
    }

    // ---- fused epilogue: t = |w|*(cos-1); rowsum += exp(t); pos = t ----
    const float wabs = fabsf(*wp);
    const float nw = -wabs;
    const int q = lane >> 2, qi = lane & 3;
    const int cbase = c0 + wn * 32;

#pragma unroll
    for (int mt = 0; mt < 4; mt++) {
        const int rowA = r0 + wm * 64 + mt * 16 + q;
        const int rowB = rowA + 8;
        const int posA = rowA / Mm, posB = rowB / Mm;
        float sA = 0.f, sB = 0.f;
#pragma unroll
        for (int nt = 0; nt < 4; nt++) {
            const int col = cbase + nt * 8 + qi * 2;
            float2 vA = __half22float2(*(__half2*)&acc[mt][nt][0]);
            float2 vB = __half22float2(*(__half2*)&acc[mt][nt][1]);
            float t0 = fmaf(wabs, vA.x, nw);
            float t1 = fmaf(wabs, vA.y, nw);
            float t2 = fmaf(wabs, vB.x, nw);
            float t3 = fmaf(wabs, vB.y, nw);
            sA += __expf(t0) + __expf(t1);
            sB += __expf(t2) + __expf(t3);
            if (col == posA) g_pos[rowA] = t0;
            if (col + 1 == posA) g_pos[rowA] = t1;
            if (col == posB) g_pos[rowB] = t2;
            if (col + 1 == posB) g_pos[rowB] = t3;
        }
#pragma unroll
        for (int off = 2; off > 0; off >>= 1) {
            sA += __shfl_xor_sync(0xffffffffu, sA, off);
            sB += __shfl_xor_sync(0xffffffffu, sB, off);
        }
        if (qi == 0) {
            atomicAdd(&g_rowsum[rowA], sA);
            atomicAdd(&g_rowsum[rowB], sB);
        }
    }
}

// ---------------------------------------------------------------------------
// Kernel 3: loss = mean_r( log(rowsum[r]) - pos_t[r] )   (shift cancels)
// ---------------------------------------------------------------------------
__global__ void loss_kernel(float* __restrict__ out) {
    __shared__ float red[256];
    float s = 0.f;
    for (int r = threadIdx.x; r < ROWS; r += 256)
        s += __logf(g_rowsum[r]) - g_pos[r];
    red[threadIdx.x] = s;
    __syncthreads();
    for (int off = 128; off > 0; off >>= 1) {
        if (threadIdx.x < off) red[threadIdx.x] += red[threadIdx.x + off];
        __syncthreads();
    }
    if (threadIdx.x == 0) out[0] = red[0] / (float)ROWS;
}

// ---------------------------------------------------------------------------
extern "C" void kernel_launch(void* const* d_in, const int* in_sizes, int n_in,
                              void* d_out, int out_size) {
    const float* emb = (const float*)d_in[0];
    const float* w   = (const float*)d_in[1];
    const float* b   = (const float*)d_in[2];
    (void)b;
    float* out = (float*)d_out;

    static int smem_set = 0;
    if (!smem_set) {
        cudaFuncSetAttribute(gemm_lse_kernel,
                             cudaFuncAttributeMaxDynamicSharedMemorySize, SMEM_BYTES);
        smem_set = 1;
    }

    prep_kernel<<<Nn, 320>>>(emb);
    gemm_lse_kernel<<<dim3(Nn / 128, ROWS / 128), 256, SMEM_BYTES>>>(w, b);
    loss_kernel<<<1, 256>>>(out);
}